// round 16
// baseline (speedup 1.0000x reference)
#include <cuda_runtime.h>
#include <cuda_fp16.h>
#include <math.h>
#include <stdint.h>

#define BB  32
#define MM  2048
#define QSd 1024
#define KSd 1024
#define Hd  1024
#define CSd 128
#define RR  (BB*MM)     // 65536 rows
#define G3  384
#define KC  1152        // concat K = KS + CS

// ---------------- scratch (static device globals) ----------------
static __device__ float g_q[BB*Hd];
static __device__ float g_qc[BB*Hd];
static __device__ float g_qg2[BB*G3];
static __device__ float g_av[G3];
static __device__ float g_part[(size_t)RR*4];
static __device__ float g_GX[(size_t)RR*G3];
static __device__ float g_GH[(size_t)RR*G3];
static __device__ float g_Wfp[8][(size_t)G3*KC];     // wfuse split-K partials
static __device__ int   g_isI32;
static __device__ int   g_cnt[BB];                    // scores completion counters
// fp16 operands
static __device__ __half g_Af16[(size_t)RR*KC];      // [memory|coverage]
static __device__ __half g_WBh[(size_t)1024*KC];     // [Wk|Wc]
static __device__ __half g_WFh[(size_t)G3*KC];       // wih @ [Wkc|Wcc]
static __device__ __half g_WHh[(size_t)G3*CSd];      // gwhh

// ---------------- PTX helpers (base ISA, sm_80+) ----------------
__device__ __forceinline__ uint32_t s2u(const void* p){
    uint32_t a;
    asm("{ .reg .u64 t; cvta.to.shared.u64 t, %1; cvt.u32.u64 %0, t; }" : "=r"(a) : "l"(p));
    return a;
}
#define CP16(dst, gsrc) \
    asm volatile("cp.async.cg.shared.global [%0], [%1], 16;" \
                 :: "r"(dst), "l"(__cvta_generic_to_global(gsrc)) : "memory")
#define CPCOMMIT() asm volatile("cp.async.commit_group;" ::: "memory")
template<int N> __device__ __forceinline__ void cpwait(){
    asm volatile("cp.async.wait_group %0;" :: "n"(N) : "memory");
}
__device__ __forceinline__ void ldsm4(uint32_t* r, uint32_t addr){
    asm volatile("ldmatrix.sync.aligned.m8n8.x4.shared.b16 {%0,%1,%2,%3}, [%4];"
        : "=r"(r[0]), "=r"(r[1]), "=r"(r[2]), "=r"(r[3]) : "r"(addr));
}
__device__ __forceinline__ void mmaf16(float* d, const uint32_t* a, const uint32_t* b){
    asm volatile("mma.sync.aligned.m16n8k16.row.col.f32.f16.f16.f32 "
        "{%0,%1,%2,%3}, {%4,%5,%6,%7}, {%8,%9}, {%0,%1,%2,%3};"
        : "+f"(d[0]), "+f"(d[1]), "+f"(d[2]), "+f"(d[3])
        : "r"(a[0]), "r"(a[1]), "r"(a[2]), "r"(a[3]), "r"(b[0]), "r"(b[1]));
}

#define SROW   80
#define ATILE  (128*SROW)          // 10240 bytes

// ============================================================
// prep1: one heterogeneous launch of all independent prep work.
//   bid 0                     : mask dtype detect + zero counters
//   bid [1, 1+216)            : wfuse split-K partials
//   bid [217, 217+4096)       : qprep (q/qc projections)
//   bid [4313, 4313+37464)    : conv_all (WB, WH, A -> fp16)
// ============================================================
#define PRE_WF   1
#define PRE_QP   (PRE_WF + 216)
#define PRE_CV   (PRE_QP + 4096)
#define PRE_TOT  (PRE_CV + 37464)

__global__ __launch_bounds__(256)
void prep1(const void* __restrict__ maskp,
           const float* __restrict__ query,
           const float* __restrict__ Wq,  const float* __restrict__ bq,
           const float* __restrict__ bk,  const float* __restrict__ bc,
           const float* __restrict__ Wqc, const float* __restrict__ bqc,
           const float* __restrict__ bkc, const float* __restrict__ bcc,
           const float* __restrict__ bac,
           const float* __restrict__ Wkc, const float* __restrict__ Wcc,
           const float* __restrict__ wih,
           const float* __restrict__ Wk,  const float* __restrict__ Wc,
           const float* __restrict__ gwhh,
           const float* __restrict__ memory, const float* __restrict__ coverage)
{
    const int tid = threadIdx.x;
    int bid = blockIdx.x;

    if (bid == 0) {
        // mask dtype detect + zero batch counters
        __shared__ unsigned int ured[256];
        const unsigned char* mbp = (const unsigned char*)maskp;
        unsigned int orr = 0;
        for (int i = tid; i < BB*MM; i += 256)
            if (i & 3) orr |= mbp[i];
        ured[tid] = orr;
        __syncthreads();
        for (int s = 128; s; s >>= 1) {
            if (tid < s) ured[tid] |= ured[tid + s];
            __syncthreads();
        }
        if (!tid) g_isI32 = (ured[0] == 0) ? 1 : 0;
        if (tid < BB) g_cnt[tid] = 0;
        return;
    }
    if (bid < PRE_QP) {
        // ---- wfuse split-K partial ----
        bid -= PRE_WF;
        __shared__ __align__(16) float as[8][132];
        __shared__ __align__(16) float bs[8][132];
        const int tx = tid & 15, ty = tid >> 4;
        const int lr = tid >> 1, lk = (tid & 1) * 4;
        const int slice = bid / 27;
        const int t27   = bid % 27;
        const int row0 = (t27 / 9) * 128;
        const int col0 = (t27 % 9) * 128;
        const int ks   = slice * 128;
        const int kk8 = tid >> 5, c4 = (tid & 31) * 4;

        float acc[8][8];
        #pragma unroll
        for (int i = 0; i < 8; ++i)
            #pragma unroll
            for (int j = 0; j < 8; ++j) acc[i][j] = 0.f;

        for (int k0 = ks; k0 < ks + 128; k0 += 8) {
            float4 av4 = *(const float4*)(wih + (size_t)(row0 + lr) * Hd + k0 + lk);
            float4 wv;
            if (col0 < KSd)
                wv = *(const float4*)(Wkc + (size_t)(k0 + kk8) * KSd + col0 + c4);
            else
                wv = *(const float4*)(Wcc + (size_t)(k0 + kk8) * CSd + (col0 - KSd) + c4);
            __syncthreads();
            as[lk+0][lr] = av4.x; as[lk+1][lr] = av4.y;
            as[lk+2][lr] = av4.z; as[lk+3][lr] = av4.w;
            *(float4*)&bs[kk8][c4] = wv;
            __syncthreads();
            #pragma unroll
            for (int kk = 0; kk < 8; ++kk) {
                float ar[8], br[8];
                #pragma unroll
                for (int i = 0; i < 4; ++i) { ar[i] = as[kk][ty*4+i]; ar[4+i] = as[kk][64+ty*4+i]; }
                #pragma unroll
                for (int j = 0; j < 4; ++j) { br[j] = bs[kk][tx*4+j]; br[4+j] = bs[kk][64+tx*4+j]; }
                #pragma unroll
                for (int i = 0; i < 8; ++i)
                    #pragma unroll
                    for (int j = 0; j < 8; ++j)
                        acc[i][j] += ar[i] * br[j];
            }
        }
        float* dst = g_Wfp[slice];
        #pragma unroll
        for (int i = 0; i < 8; ++i) {
            int r = row0 + ((i < 4) ? (ty*4 + i) : (64 + ty*4 + i - 4));
            #pragma unroll
            for (int jh = 0; jh < 2; ++jh) {
                int cb = col0 + jh*64 + tx*4;
                float4 v; v.x = acc[i][jh*4+0]; v.y = acc[i][jh*4+1];
                v.z = acc[i][jh*4+2]; v.w = acc[i][jh*4+3];
                *(float4*)(dst + (size_t)r * KC + cb) = v;
            }
        }
        return;
    }
    if (bid < PRE_CV) {
        // ---- qprep ----
        int gw   = (bid - PRE_QP) * 8 + (tid >> 5);
        int lane = tid & 31;
        if (gw >= BB*Hd) return;
        int b = gw >> 10, h = gw & 1023;
        const float* q  = query + (size_t)b * QSd;
        const float* w1 = Wq  + (size_t)h * QSd;
        const float* w2 = Wqc + (size_t)h * QSd;
        float a1 = 0.f, a2 = 0.f;
        for (int k = lane; k < QSd; k += 32) {
            float qv = q[k];
            a1 += qv * w1[k];
            a2 += qv * w2[k];
        }
        #pragma unroll
        for (int o = 16; o; o >>= 1) {
            a1 += __shfl_xor_sync(0xffffffffu, a1, o);
            a2 += __shfl_xor_sync(0xffffffffu, a2, o);
        }
        if (!lane) {
            g_q[gw]  = a1 + bq[h]  + bk[h]  + bc[h];
            g_qc[gw] = a2 + bqc[h] + bkc[h] + bcc[h] + bac[h];
        }
        return;
    }
    // ---- conversions ----
    bid -= PRE_CV;
    if (bid < 576) {
        long long t = (long long)bid * 256 + tid;
        long long e = t * 8;
        int c = (int)(e % KC);
        long long r = e / KC;
        float4 v0, v1;
        if (c < KSd) { const float4* p = (const float4*)(Wk + r * KSd + c); v0 = p[0]; v1 = p[1]; }
        else         { const float4* p = (const float4*)(Wc + r * CSd + (c - KSd)); v0 = p[0]; v1 = p[1]; }
        float v[8] = {v0.x,v0.y,v0.z,v0.w,v1.x,v1.y,v1.z,v1.w};
        __align__(16) __half hv[8];
        #pragma unroll
        for (int j = 0; j < 8; ++j) hv[j] = __float2half_rn(v[j]);
        *(uint4*)(g_WBh + r * KC + c) = *(uint4*)hv;
    } else if (bid < 600) {
        long long t = (long long)(bid - 576) * 256 + tid;
        long long e = t * 8;
        const float4* p = (const float4*)(gwhh + e);
        float4 v0 = p[0], v1 = p[1];
        float v[8] = {v0.x,v0.y,v0.z,v0.w,v1.x,v1.y,v1.z,v1.w};
        __align__(16) __half hv[8];
        #pragma unroll
        for (int j = 0; j < 8; ++j) hv[j] = __float2half_rn(v[j]);
        *(uint4*)(g_WHh + e) = *(uint4*)hv;
    } else {
        long long t = (long long)(bid - 600) * 256 + tid;
        long long e = t * 8;
        int c = (int)(e % KC);
        long long r = e / KC;
        float4 v0, v1;
        if (c < KSd) { const float4* p = (const float4*)(memory + r * KSd + c); v0 = p[0]; v1 = p[1]; }
        else         { const float4* p = (const float4*)(coverage + r * CSd + (c - KSd)); v0 = p[0]; v1 = p[1]; }
        float v[8] = {v0.x,v0.y,v0.z,v0.w,v1.x,v1.y,v1.z,v1.w};
        __align__(16) __half hv[8];
        #pragma unroll
        for (int j = 0; j < 8; ++j) hv[j] = __float2half_rn(v[j]);
        *(uint4*)(g_Af16 + r * KC + c) = *(uint4*)hv;
    }
}

// ============================================================
// prep2m: prep2 (qg2/av) + wfuse_reduce merged.
//   bid [0, 1584)       : prep2 warps
//   bid [1584, 1584+432): wfuse reduce -> fp16
// ============================================================
__global__ void prep2m(const float* __restrict__ wih, const float* __restrict__ bih,
                       const float* __restrict__ Wac)
{
    int bid = blockIdx.x;
    const int tid = threadIdx.x;
    if (bid < 1584) {
        int gw   = bid * 8 + (tid >> 5);
        int lane = tid & 31;
        if (gw >= 33*G3) return;
        if (gw < 32*G3) {
            int b = gw / G3, g = gw % G3;
            const float* x  = g_qc + (size_t)b * Hd;
            const float* wr = wih  + (size_t)g * Hd;
            float a = 0.f;
            for (int h = lane; h < Hd; h += 32) a += x[h] * wr[h];
            #pragma unroll
            for (int o = 16; o; o >>= 1) a += __shfl_xor_sync(0xffffffffu, a, o);
            if (!lane) g_qg2[gw] = a + bih[g];
        } else {
            int g = gw - 32*G3;
            const float* wr = wih + (size_t)g * Hd;
            float a = 0.f;
            for (int h = lane; h < Hd; h += 32) a += Wac[h] * wr[h];
            #pragma unroll
            for (int o = 16; o; o >>= 1) a += __shfl_xor_sync(0xffffffffu, a, o);
            if (!lane) g_av[g] = a;
        }
        return;
    }
    int base = ((bid - 1584) * 256 + tid) * 4;
    if (base >= G3*KC) return;
    float4 s = *(const float4*)(g_Wfp[0] + base);
    #pragma unroll
    for (int p = 1; p < 8; ++p) {
        float4 v = *(const float4*)(g_Wfp[p] + base);
        s.x += v.x; s.y += v.y; s.z += v.z; s.w += v.w;
    }
    __align__(8) __half hv[4];
    hv[0] = __float2half_rn(s.x); hv[1] = __float2half_rn(s.y);
    hv[2] = __float2half_rn(s.z); hv[3] = __float2half_rn(s.w);
    *(uint2*)(g_WFh + base) = *(uint2*)hv;
}

// ============================================================
// scores_k: fp16 GEMM 128x256 + fused per-batch softmax (last-CTA pattern).
// 64 CTAs per batch (16 row-tiles x 4 col-tiles); the 64th computes softmax.
// ============================================================
#define NT0   256
#define STG0  (uint32_t)(ATILE + NT0*SROW)   // 30720
#define DSM0  (4 * (int)STG0)                // 122880

__global__ __launch_bounds__(256)
void scores_k(const float* __restrict__ Wl, const void* __restrict__ maskp,
              const float* __restrict__ bl, float* __restrict__ wout)
{
    constexpr int NST = KC/32, NF = 8;
    extern __shared__ __align__(16) char dsm[];
    const uint32_t sbase = s2u(dsm);

    const int tid = threadIdx.x;
    const int wid = tid >> 5, lane = tid & 31;
    const int ct = blockIdx.x & 3, rt = blockIdx.x >> 2;
    const int row0 = rt * 128, col0 = ct * NT0;
    const int wm = (wid & 1) * 64;
    const int wn = (wid >> 1) * 64;

    auto load_stage = [&](int s, int stg) {
        const uint32_t sb = sbase + (uint32_t)stg * STG0;
        const int kc = s * 32;
        #pragma unroll
        for (int j = 0; j < 2; ++j) {
            int idx = tid + j*256;
            int r = idx >> 2, cu = idx & 3;
            CP16(sb + (uint32_t)(r*SROW + cu*16),
                 g_Af16 + (size_t)(row0 + r) * KC + kc + cu*8);
        }
        #pragma unroll
        for (int j = 0; j < 4; ++j) {
            int idx = tid + j*256;
            int r = idx >> 2, cu = idx & 3;
            CP16(sb + (uint32_t)ATILE + (uint32_t)(r*SROW + cu*16),
                 g_WBh + (size_t)(col0 + r) * KC + kc + cu*8);
        }
    };

    float acc[4][NF][4];
    #pragma unroll
    for (int i = 0; i < 4; ++i)
        #pragma unroll
        for (int j = 0; j < NF; ++j)
            #pragma unroll
            for (int k = 0; k < 4; ++k) acc[i][j][k] = 0.f;

    const int arow = wm + (lane & 7) + ((lane >> 3) & 1) * 8;
    const uint32_t akb = (uint32_t)(((lane >> 4) & 1) * 16);
    const int brow = wn + (lane & 7) + ((lane >> 4) & 1) * 8;
    const uint32_t bkb = (uint32_t)(((lane >> 3) & 1) * 16);

    #pragma unroll
    for (int i = 0; i < 3; ++i) { load_stage(i, i); CPCOMMIT(); }

    for (int s = 0; s < NST; ++s) {
        if (s + 3 < NST) { load_stage(s + 3, (s + 3) & 3); CPCOMMIT(); cpwait<3>(); }
        else             { cpwait<0>(); }
        __syncthreads();
        const uint32_t sb = sbase + (uint32_t)(s & 3) * STG0;
        #pragma unroll
        for (int kh = 0; kh < 2; ++kh) {
            const uint32_t ko = (uint32_t)(kh * 32);
            uint32_t a[4][4], b[NF][2];
            #pragma unroll
            for (int mi = 0; mi < 4; ++mi)
                ldsm4(a[mi], sb + (uint32_t)((arow + mi*16) * SROW) + ko + akb);
            #pragma unroll
            for (int ni = 0; ni < NF; ni += 2)
                ldsm4(&b[ni][0], sb + (uint32_t)ATILE + (uint32_t)((brow + ni*8) * SROW) + ko + bkb);
            #pragma unroll
            for (int mi = 0; mi < 4; ++mi)
                #pragma unroll
                for (int ni = 0; ni < NF; ++ni)
                    mmaf16(acc[mi][ni], a[mi], b[ni]);
        }
        __syncthreads();
    }

    const int gq4 = lane >> 2;
    const int q   = lane & 3;
    const int bIdx = row0 >> 11;

    float* red = (float*)dsm;
    float rowsum[4][2];
    #pragma unroll
    for (int mi = 0; mi < 4; ++mi)
        #pragma unroll
        for (int hf = 0; hf < 2; ++hf) {
            float s = 0.f;
            #pragma unroll
            for (int ni = 0; ni < NF; ++ni) {
                int c = col0 + wn + ni*8 + q*2;
                float v0 = acc[mi][ni][hf*2+0] + g_q[bIdx*Hd + c];
                float v1 = acc[mi][ni][hf*2+1] + g_q[bIdx*Hd + c + 1];
                s += tanhf(v0) * Wl[c] + tanhf(v1) * Wl[c+1];
            }
            s += __shfl_xor_sync(0xffffffffu, s, 1);
            s += __shfl_xor_sync(0xffffffffu, s, 2);
            rowsum[mi][hf] = s;
        }
    if (q == 0) {
        #pragma unroll
        for (int mi = 0; mi < 4; ++mi)
            #pragma unroll
            for (int hf = 0; hf < 2; ++hf) {
                int lr = wm + mi*16 + gq4 + hf*8;
                red[(wid >> 1) * 128 + lr] = rowsum[mi][hf];
            }
    }
    __syncthreads();
    if (tid < 128) {
        float s = red[tid] + red[128 + tid] + red[256 + tid] + red[384 + tid];
        g_part[(size_t)(row0 + tid) * 4 + ct] = s;
    }

    // ---- last-CTA-per-batch fused softmax ----
    __shared__ int s_old;
    __threadfence();
    __syncthreads();
    if (!tid) s_old = atomicAdd(&g_cnt[bIdx], 1);
    __syncthreads();
    if (s_old != 63) return;

    // this CTA is the 64th for batch bIdx: do its softmax
    float* sv = (float*)dsm;               // [MM]
    float* sred = sv + MM;                 // [256]
    const bool isI32 = (g_isI32 != 0);
    const unsigned char* mbp = (const unsigned char*)maskp;
    const float blv = bl[0];
    const int b = bIdx;

    for (int m = tid; m < MM; m += 256) {
        bool pad = isI32 ? (((const int*)maskp)[b*MM + m] != 0)
                         : (mbp[b*MM + m] != 0);
        if (pad) sv[m] = -1e30f;
        else {
            const float* p = g_part + (size_t)(b*MM + m) * 4;
            sv[m] = (p[0] + p[1]) + (p[2] + p[3]) + blv;
        }
    }
    __syncthreads();

    float mx = -3.4e38f;
    for (int m = tid; m < MM; m += 256) mx = fmaxf(mx, sv[m]);
    sred[tid] = mx;
    __syncthreads();
    for (int s = 128; s; s >>= 1) { if (tid < s) sred[tid] = fmaxf(sred[tid], sred[tid + s]); __syncthreads(); }
    mx = sred[0];
    __syncthreads();

    float sum = 0.f;
    for (int m = tid; m < MM; m += 256) { float e = expf(sv[m] - mx); sv[m] = e; sum += e; }
    sred[tid] = sum;
    __syncthreads();
    for (int s = 128; s; s >>= 1) { if (tid < s) sred[tid] += sred[tid + s]; __syncthreads(); }
    float inv = 1.f / sred[0];
    __syncthreads();

    for (int m = tid; m < MM; m += 256) wout[b*MM + m] = sv[m] * inv;
}

// ============================================================
// postk: merged attns + gx + gh (one launch after scores).
// ============================================================
#define NT1   192
#define STG1  (uint32_t)(ATILE + NT1*SROW)   // 25600
#define DSMP  (4 * (int)STG1)                // 102400

__global__ __launch_bounds__(256)
void postk(const float* __restrict__ memory, const float* __restrict__ w,
           float* __restrict__ out_attn, const float* __restrict__ gbhh)
{
    extern __shared__ __align__(16) char dsm[];
    const int tid = threadIdx.x;
    int bid = blockIdx.x;

    if (bid < 128) {
        // ---- attns ----
        float* ws = (float*)dsm;
        const int b = bid >> 2;
        const int k = (bid & 3) * 256 + tid;
        for (int i = tid; i < MM; i += 256) ws[i] = w[b*MM + i];
        __syncthreads();
        const float* mp = memory + (size_t)b * MM * KSd + k;
        float a0 = 0.f, a1 = 0.f, a2 = 0.f, a3 = 0.f;
        for (int m = 0; m < MM; m += 4) {
            a0 += ws[m+0] * mp[(size_t)(m+0) * KSd];
            a1 += ws[m+1] * mp[(size_t)(m+1) * KSd];
            a2 += ws[m+2] * mp[(size_t)(m+2) * KSd];
            a3 += ws[m+3] * mp[(size_t)(m+3) * KSd];
        }
        out_attn[b*KSd + k] = (a0 + a1) + (a2 + a3);
        return;
    }
    bid -= 128;
    const bool isGX = bid < 1024;
    if (!isGX) bid -= 1024;

    const __half* Bp = isGX ? g_WFh : g_WHh;
    const int BSTR = isGX ? KC : CSd;
    const int AOFF = isGX ? 0 : KSd;
    const int NST  = isGX ? (KC/32) : (CSd/32);

    const uint32_t sbase = s2u(dsm);
    const int wid = tid >> 5, lane = tid & 31;
    const int ct = bid & 1, rt = bid >> 1;
    const int row0 = rt * 128, col0 = ct * NT1;
    const int wm = (wid & 1) * 64;
    const int wn = (wid >> 1) * 48;

    auto load_stage = [&](int s, int stg) {
        const uint32_t sb = sbase + (uint32_t)stg * STG1;
        const int kc = s * 32;
        #pragma unroll
        for (int j = 0; j < 2; ++j) {
            int idx = tid + j*256;
            int r = idx >> 2, cu = idx & 3;
            CP16(sb + (uint32_t)(r*SROW + cu*16),
                 g_Af16 + (size_t)(row0 + r) * KC + AOFF + kc + cu*8);
        }
        #pragma unroll
        for (int j = 0; j < 3; ++j) {
            int idx = tid + j*256;
            int r = idx >> 2, cu = idx & 3;
            CP16(sb + (uint32_t)ATILE + (uint32_t)(r*SROW + cu*16),
                 Bp + (size_t)(col0 + r) * BSTR + kc + cu*8);
        }
    };

    float acc[4][6][4];
    #pragma unroll
    for (int i = 0; i < 4; ++i)
        #pragma unroll
        for (int j = 0; j < 6; ++j)
            #pragma unroll
            for (int k = 0; k < 4; ++k) acc[i][j][k] = 0.f;

    const int arow = wm + (lane & 7) + ((lane >> 3) & 1) * 8;
    const uint32_t akb = (uint32_t)(((lane >> 4) & 1) * 16);
    const int brow = wn + (lane & 7) + ((lane >> 4) & 1) * 8;
    const uint32_t bkb = (uint32_t)(((lane >> 3) & 1) * 16);

    for (int i = 0; i < 3; ++i) { load_stage(i, i); CPCOMMIT(); }

    for (int s = 0; s < NST; ++s) {
        if (s + 3 < NST) { load_stage(s + 3, (s + 3) & 3); CPCOMMIT(); cpwait<3>(); }
        else             { cpwait<0>(); }
        __syncthreads();
        const uint32_t sb = sbase + (uint32_t)(s & 3) * STG1;
        #pragma unroll
        for (int kh = 0; kh < 2; ++kh) {
            const uint32_t ko = (uint32_t)(kh * 32);
            uint32_t a[4][4], b[6][2];
            #pragma unroll
            for (int mi = 0; mi < 4; ++mi)
                ldsm4(a[mi], sb + (uint32_t)((arow + mi*16) * SROW) + ko + akb);
            #pragma unroll
            for (int ni = 0; ni < 6; ni += 2)
                ldsm4(&b[ni][0], sb + (uint32_t)ATILE + (uint32_t)((brow + ni*8) * SROW) + ko + bkb);
            #pragma unroll
            for (int mi = 0; mi < 4; ++mi)
                #pragma unroll
                for (int ni = 0; ni < 6; ++ni)
                    mmaf16(acc[mi][ni], a[mi], b[ni]);
        }
        __syncthreads();
    }

    const int gq4 = lane >> 2;
    const int q   = lane & 3;
    const int bIdx = row0 >> 11;

    if (isGX) {
        #pragma unroll
        for (int mi = 0; mi < 4; ++mi)
            #pragma unroll
            for (int hf = 0; hf < 2; ++hf) {
                int r = row0 + wm + mi*16 + gq4 + hf*8;
                float wr = w[r];
                #pragma unroll
                for (int ni = 0; ni < 6; ++ni) {
                    int c = col0 + wn + ni*8 + q*2;
                    float2 v;
                    v.x = acc[mi][ni][hf*2+0] + g_qg2[bIdx*G3 + c  ] + wr * g_av[c  ];
                    v.y = acc[mi][ni][hf*2+1] + g_qg2[bIdx*G3 + c+1] + wr * g_av[c+1];
                    *(float2*)(g_GX + (size_t)r * G3 + c) = v;
                }
            }
    } else {
        #pragma unroll
        for (int mi = 0; mi < 4; ++mi)
            #pragma unroll
            for (int hf = 0; hf < 2; ++hf) {
                int r = row0 + wm + mi*16 + gq4 + hf*8;
                #pragma unroll
                for (int ni = 0; ni < 6; ++ni) {
                    int c = col0 + wn + ni*8 + q*2;
                    float2 v;
                    v.x = acc[mi][ni][hf*2+0] + gbhh[c  ];
                    v.y = acc[mi][ni][hf*2+1] + gbhh[c+1];
                    *(float2*)(g_GH + (size_t)r * G3 + c) = v;
                }
            }
    }
}

// ============================================================
// GRU elementwise (float4 vectorized)
// ============================================================
__global__ void gru_k(const float* __restrict__ coverage, float* __restrict__ outc)
{
    size_t idx4 = (size_t)blockIdx.x * 256 + threadIdx.x;   // < RR*32
    int r  = (int)(idx4 >> 5);
    int c4 = (int)(idx4 & 31) * 4;
    size_t gi = (size_t)r * G3 + c4;
    float4 xr = *(const float4*)(g_GX + gi);
    float4 xz = *(const float4*)(g_GX + gi + 128);
    float4 xn = *(const float4*)(g_GX + gi + 256);
    float4 hr = *(const float4*)(g_GH + gi);
    float4 hz = *(const float4*)(g_GH + gi + 128);
    float4 hn = *(const float4*)(g_GH + gi + 256);
    float4 cv = *(const float4*)(coverage + (size_t)r * CSd + c4);
    float4 o;
    {
        float rg = 1.f / (1.f + expf(-(xr.x + hr.x)));
        float z  = 1.f / (1.f + expf(-(xz.x + hz.x)));
        float n  = tanhf(xn.x + rg * hn.x);
        o.x = (1.f - z) * n + z * cv.x;
    }
    {
        float rg = 1.f / (1.f + expf(-(xr.y + hr.y)));
        float z  = 1.f / (1.f + expf(-(xz.y + hz.y)));
        float n  = tanhf(xn.y + rg * hn.y);
        o.y = (1.f - z) * n + z * cv.y;
    }
    {
        float rg = 1.f / (1.f + expf(-(xr.z + hr.z)));
        float z  = 1.f / (1.f + expf(-(xz.z + hz.z)));
        float n  = tanhf(xn.z + rg * hn.z);
        o.z = (1.f - z) * n + z * cv.z;
    }
    {
        float rg = 1.f / (1.f + expf(-(xr.w + hr.w)));
        float z  = 1.f / (1.f + expf(-(xz.w + hz.w)));
        float n  = tanhf(xn.w + rg * hn.w);
        o.w = (1.f - z) * n + z * cv.w;
    }
    *(float4*)(outc + (size_t)r * CSd + c4) = o;
}

// ============================================================
extern "C" void kernel_launch(void* const* d_in, const int* in_sizes, int n_in,
                              void* d_out, int out_size)
{
    const float* query   = (const float*)d_in[0];
    const float* memory  = (const float*)d_in[1];
    const float* coverage= (const float*)d_in[2];
    const float* Wq  = (const float*)d_in[3];  const float* bq  = (const float*)d_in[4];
    const float* Wk  = (const float*)d_in[5];  const float* bk  = (const float*)d_in[6];
    const float* Wc  = (const float*)d_in[7];  const float* bc  = (const float*)d_in[8];
    const float* Wcc = (const float*)d_in[9];  const float* bcc = (const float*)d_in[10];
    const float* Wqc = (const float*)d_in[11]; const float* bqc = (const float*)d_in[12];
    const float* Wkc = (const float*)d_in[13]; const float* bkc = (const float*)d_in[14];
    const float* Wac = (const float*)d_in[15]; const float* bac = (const float*)d_in[16];
    const float* Wl  = (const float*)d_in[17]; const float* bl  = (const float*)d_in[18];
    const float* gwih= (const float*)d_in[19]; const float* gbih= (const float*)d_in[20];
    const float* gwhh= (const float*)d_in[21]; const float* gbhh= (const float*)d_in[22];
    const void*  maskp = d_in[23];

    float* out      = (float*)d_out;
    float* out_attn = out;
    float* out_w    = out + BB*KSd;
    float* out_cov  = out + BB*KSd + BB*MM;

    static int attr_done = 0;
    if (!attr_done) {
        cudaFuncSetAttribute((const void*)scores_k, cudaFuncAttributeMaxDynamicSharedMemorySize, DSM0);
        cudaFuncSetAttribute((const void*)postk,    cudaFuncAttributeMaxDynamicSharedMemorySize, DSMP);
        attr_done = 1;
    }

    // launch 1: all independent prep (mask+counters, wfuse partials, qprep, conversions)
    prep1<<<PRE_TOT, 256>>>(maskp, query, Wq, bq, bk, bc, Wqc, bqc, bkc, bcc, bac,
                            Wkc, Wcc, gwih, Wk, Wc, gwhh, memory, coverage);

    // launch 2: dependent prep (qg2/av, wfuse reduce)
    prep2m<<<1584 + 432, 256>>>(gwih, gbih, Wac);

    // launch 3: scores GEMM + fused per-batch softmax -> out_w
    scores_k<<<(RR/128)*4, 256, DSM0>>>(Wl, maskp, bl, out_w);

    // launch 4: attns + gx + gh
    postk<<<128 + 2*(RR/128)*2, 256, DSMP>>>(memory, out_w, out_attn, gbhh);

    // launch 5: GRU elementwise -> new_coverage
    gru_k<<<RR*32/256, 256>>>(coverage, out_cov);
}